// round 15
// baseline (speedup 1.0000x reference)
#include <cuda_runtime.h>
#include <math.h>

// Problem constants (B=4, S=4096, D=2048, E=8, K=2)
#define NTOK    16384
#define DIM     2048
#define NEXP    8
#define NASSIGN (NTOK*2)       // 32768
#define CAP     5120           // int(NTOK*2/8 * 1.25)
#define NTASK   (NTOK/4)       // 4096 tasks of 4 tokens
#define NBLK    152            // persistent, 1 block per SM
#define THREADS 512            // 16 warps: 8 producer + 8 consumer pairs
#define NPAIRS  8
#define RING    4              // stages per pair ring
#define STAGE_DIMS 256         // dims per stage (2 chunks of 128)
#define ROWB    (STAGE_DIMS*4) // 1024 B per token-row per stage
#define STAGEB  (4*ROWB)       // 4 KB per stage
#define RINGB   (RING*STAGEB)  // 16 KB per pair
#define W_BYTES (NEXP*DIM*4)   // 64 KB
#define SMEM_DYN (W_BYTES + NPAIRS*RINGB)   // 192 KB

// Output layout (float32): [0,32768) indices | [32768,65536) weights |
// [65536] loss | [65537,98305) mask

__device__ int      g_cnt[NEXP];
__device__ float    g_probsum[NEXP];
__device__ unsigned g_done;
__device__ unsigned g_ticket;
__device__ unsigned long long g_bucket[NEXP][NASSIGN];

__device__ __forceinline__ void ffma2(unsigned long long& d,
                                      unsigned long long a,
                                      unsigned long long b) {
    asm("fma.rn.f32x2 %0, %1, %2, %0;" : "+l"(d) : "l"(a), "l"(b));
}
__device__ __forceinline__ float unpack_sum(unsigned long long v) {
    unsigned lo, hi;
    asm("mov.b64 {%0, %1}, %2;" : "=r"(lo), "=r"(hi) : "l"(v));
    return __uint_as_float(lo) + __uint_as_float(hi);
}
__device__ __forceinline__ unsigned smem_u32(const void* p) {
    return (unsigned)__cvta_generic_to_shared(p);
}
__device__ __forceinline__ void cp_async16(unsigned dst, const void* src) {
    asm volatile("cp.async.cg.shared.global [%0], [%1], 16;"
                 :: "r"(dst), "l"(src) : "memory");
}
// Arrive on mbarrier when ALL prior cp.async of this thread complete.
// (non-noinc form: increments pending count at issue, arrives at completion)
__device__ __forceinline__ void cp_mbar_arrive(unsigned mb) {
    asm volatile("cp.async.mbarrier.arrive.shared.b64 [%0];"
                 :: "r"(mb) : "memory");
}
__device__ __forceinline__ void mbar_init(unsigned mb, unsigned cnt) {
    asm volatile("mbarrier.init.shared.b64 [%0], %1;" :: "r"(mb), "r"(cnt) : "memory");
}
__device__ __forceinline__ void mbar_arrive(unsigned mb) {
    asm volatile("mbarrier.arrive.shared.b64 _, [%0];" :: "r"(mb) : "memory");
}
__device__ __forceinline__ void mbar_wait(unsigned mb, unsigned parity) {
    asm volatile(
        "{\n\t.reg .pred P;\n\t"
        "W_%=:\n\t"
        "mbarrier.try_wait.parity.acquire.cta.shared::cta.b64 P, [%0], %1, 0x989680;\n\t"
        "@P bra D_%=;\n\t"
        "bra W_%=;\n\t"
        "D_%=:\n\t}"
        :: "r"(mb), "r"(parity) : "memory");
}
__device__ __forceinline__ int grab_task(int lane) {
    int t = 0;
    if (lane == 0) t = (int)atomicAdd(&g_ticket, 1u);
    return __shfl_sync(0xffffffffu, t, 0);
}

// Warp-specialized persistent kernel. Producer warp p streams x for 4-token
// tasks into a private 4-stage cp.async ring; consumer warp p+8 computes
// GEMV/softmax/top-2 with zero gmem loads. Per-stage mbarrier pairs:
//   full[s]:  count 1 (producer lane0 explicit arrive) + 32 dynamic
//             cp.async arrivals; meta word carries the task id (-1 = poison)
//   empty[s]: count 1 (consumer lane0 arrives after consuming)
// LAST arriving block computes loss + (rare) capacity drop + resets scratch.
__global__ __launch_bounds__(THREADS, 1)
void router_main(const float* __restrict__ x,
                 const float* __restrict__ wg,
                 float* __restrict__ out) {
    extern __shared__ float sw[];           // w 64 KB, rings after
    __shared__ __align__(8) unsigned long long mb_full[NPAIRS][RING];
    __shared__ __align__(8) unsigned long long mb_empty[NPAIRS][RING];
    __shared__ int   s_meta[NPAIRS][RING];
    __shared__ float s_prob[NEXP];
    __shared__ int   s_last;

    const int tid  = threadIdx.x;
    const int warp = tid >> 5;
    const int lane = tid & 31;
    if (tid < NEXP) s_prob[tid] = 0.0f;

    if (tid < NPAIRS * RING) {
        int p = tid / RING, s = tid % RING;
        mbar_init(smem_u32(&mb_full[p][s]), 1);
        mbar_init(smem_u32(&mb_empty[p][s]), 1);
    }

    // stage w_gate once per persistent block
    {
        float4* sw4 = (float4*)sw;
        const float4* wg4 = (const float4*)wg;
        #pragma unroll
        for (int i = tid; i < NEXP * DIM / 4; i += THREADS) sw4[i] = wg4[i];
    }
    __syncthreads();
    asm volatile("fence.proxy.async.shared::cta;" ::: "memory");

    const int pair = warp & 7;
    char* ring = (char*)sw + W_BYTES + pair * RINGB;
    const unsigned ring_u = smem_u32(ring);
    const unsigned lane16 = lane * 16;

    if (warp < NPAIRS) {
        // ================= PRODUCER =================
        int ps = 0, pp = 1;                    // empty-wait cursor (phase 1)
        int task = grab_task(lane);
        for (;;) {
            if (task < NTASK) {
                const char* xg = (const char*)x + (size_t)(task * 4) * (DIM * 4);
                #pragma unroll 2
                for (int k = 0; k < 8; k++) {  // 8 stages per task
                    if (lane == 0) mbar_wait(smem_u32(&mb_empty[pair][ps]), pp);
                    __syncwarp();
                    unsigned dst = ring_u + ps * STAGEB + lane16;
                    #pragma unroll
                    for (int r = 0; r < 4; r++) {
                        const char* srow = xg + (size_t)r * (DIM * 4) + k * ROWB + lane16;
                        cp_async16(dst + r * ROWB,       srow);
                        cp_async16(dst + r * ROWB + 512, srow + 512);
                    }
                    cp_mbar_arrive(smem_u32(&mb_full[pair][ps]));
                    __syncwarp();               // all 32 increments issued
                    if (lane == 0) {
                        s_meta[pair][ps] = task;
                        mbar_arrive(smem_u32(&mb_full[pair][ps]));
                    }
                    if (++ps == RING) { ps = 0; pp ^= 1; }
                }
                task = grab_task(lane);
            } else {
                // poison stage
                if (lane == 0) mbar_wait(smem_u32(&mb_empty[pair][ps]), pp);
                __syncwarp();
                cp_mbar_arrive(smem_u32(&mb_full[pair][ps]));   // immediate
                __syncwarp();
                if (lane == 0) {
                    s_meta[pair][ps] = -1;
                    mbar_arrive(smem_u32(&mb_full[pair][ps]));
                }
                break;
            }
        }
    } else {
        // ================= CONSUMER =================
        const ulonglong2* sw2 = (const ulonglong2*)sw;
        int cs = 0, cp = 0;                    // full-wait cursor (phase 0)
        for (;;) {
            if (lane == 0) mbar_wait(smem_u32(&mb_full[pair][cs]), cp);
            __syncwarp();                       // syncwarp = warp memory fence
            const int task = s_meta[pair][cs];
            if (task < 0) break;

            unsigned long long acc[4][NEXP];
            #pragma unroll
            for (int t = 0; t < 4; t++)
                #pragma unroll
                for (int e = 0; e < NEXP; e++) acc[t][e] = 0ull;

            #pragma unroll 2
            for (int k = 0; k < 8; k++) {
                if (k > 0) {
                    if (lane == 0) mbar_wait(smem_u32(&mb_full[pair][cs]), cp);
                    __syncwarp();
                }
                const char* stg = ring + cs * STAGEB;
                #pragma unroll
                for (int c = 0; c < 2; c++) {
                    ulonglong2 xv0 = *(const ulonglong2*)(stg + 0 * ROWB + c * 512 + lane16);
                    ulonglong2 xv1 = *(const ulonglong2*)(stg + 1 * ROWB + c * 512 + lane16);
                    ulonglong2 xv2 = *(const ulonglong2*)(stg + 2 * ROWB + c * 512 + lane16);
                    ulonglong2 xv3 = *(const ulonglong2*)(stg + 3 * ROWB + c * 512 + lane16);
                    const int cc = (k * 2 + c) * 32 + lane;
                    #pragma unroll
                    for (int e = 0; e < NEXP; e++) {
                        ulonglong2 wv = sw2[e * (DIM / 4) + cc];
                        ffma2(acc[0][e], xv0.x, wv.x); ffma2(acc[0][e], xv0.y, wv.y);
                        ffma2(acc[1][e], xv1.x, wv.x); ffma2(acc[1][e], xv1.y, wv.y);
                        ffma2(acc[2][e], xv2.x, wv.x); ffma2(acc[2][e], xv2.y, wv.y);
                        ffma2(acc[3][e], xv3.x, wv.x); ffma2(acc[3][e], xv3.y, wv.y);
                    }
                }
                __syncwarp();                   // reads done before release
                if (lane == 0) mbar_arrive(smem_u32(&mb_empty[pair][cs]));
                if (++cs == RING) { cs = 0; cp ^= 1; }
            }

            // collapse + butterfly -> lanes 0-3 hold full logits
            float logit[4][NEXP];
            #pragma unroll
            for (int t = 0; t < 4; t++)
                #pragma unroll
                for (int e = 0; e < NEXP; e++) {
                    float v = unpack_sum(acc[t][e]);
                    v += __shfl_xor_sync(0xffffffffu, v, 16);
                    v += __shfl_xor_sync(0xffffffffu, v, 8);
                    v += __shfl_xor_sync(0xffffffffu, v, 4);
                    v += __shfl_xor_sync(0xffffffffu, v, 2);
                    v += __shfl_xor_sync(0xffffffffu, v, 1);
                    logit[t][e] = v;
                }

            if (lane < 4) {
                int token = task * 4 + lane;
                float p[NEXP];
                float m = logit[lane][0];
                #pragma unroll
                for (int e = 1; e < NEXP; e++) m = fmaxf(m, logit[lane][e]);
                float s = 0.0f;
                #pragma unroll
                for (int e = 0; e < NEXP; e++) { p[e] = expf(logit[lane][e] - m); s += p[e]; }
                float inv = 1.0f / s;
                #pragma unroll
                for (int e = 0; e < NEXP; e++) p[e] *= inv;

                int i1 = 0; float b1 = p[0];
                #pragma unroll
                for (int e = 1; e < NEXP; e++) if (p[e] > b1) { b1 = p[e]; i1 = e; }
                int i2 = -1; float b2 = -1.0f;
                #pragma unroll
                for (int e = 0; e < NEXP; e++) if (e != i1 && p[e] > b2) { b2 = p[e]; i2 = e; }

                float ssum = b1 + b2;
                float w1 = b1 / ssum, w2 = b2 / ssum;

                int n0 = token * 2;
                out[n0]     = (float)i1;
                out[n0 + 1] = (float)i2;
                out[NASSIGN + n0]     = w1;
                out[NASSIGN + n0 + 1] = w2;
                out[2 * NASSIGN + 1 + n0]     = 1.0f;
                out[2 * NASSIGN + 1 + n0 + 1] = 1.0f;

                int s1 = atomicAdd(&g_cnt[i1], 1);
                g_bucket[i1][s1] = ((unsigned long long)__float_as_uint(w1) << 32) |
                                   (unsigned)(~(unsigned)n0);
                int s2 = atomicAdd(&g_cnt[i2], 1);
                g_bucket[i2][s2] = ((unsigned long long)__float_as_uint(w2) << 32) |
                                   (unsigned)(~(unsigned)(n0 + 1));

                #pragma unroll
                for (int e = 0; e < NEXP; e++) atomicAdd(&s_prob[e], p[e]);
            }
        }
    }

    // all 16 warps converge here
    __syncthreads();
    if (tid < NEXP) atomicAdd(&g_probsum[tid], s_prob[tid]);
    __syncthreads();

    if (tid == 0) {
        __threadfence();
        unsigned old = atomicAdd(&g_done, 1u);
        s_last = (old == (unsigned)(gridDim.x - 1)) ? 1 : 0;
    }
    __syncthreads();
    if (!s_last) return;

    __shared__ int cnt[NEXP];
    if (tid < NEXP) cnt[tid] = __ldcg(&g_cnt[tid]);
    __syncthreads();

    if (tid == 0) {
        float imp[NEXP], imps = 0.0f;
        #pragma unroll
        for (int e = 0; e < NEXP; e++) { imp[e] = __ldcg(&g_probsum[e]); imps += imp[e]; }
        float loss = 0.0f;
        #pragma unroll
        for (int e = 0; e < NEXP; e++)
            loss += (imp[e] / imps) * ((float)cnt[e] / (float)NASSIGN);
        out[2 * NASSIGN] = (float)NEXP * loss;
    }

    // Capacity drop (rank = #{j: key > key_i}; keep iff rank < CAP). Matches
    // lexsort((-w, expert)) with flat-index tiebreak; rarely triggers.
    for (int e = 0; e < NEXP; e++) {
        int c = cnt[e];
        if (c <= CAP) continue;
        for (int i = tid; i < c; i += blockDim.x) {
            unsigned long long ki = __ldcg(&g_bucket[e][i]);
            int rank = 0;
            for (int j = 0; j < c; j++)
                rank += (__ldcg(&g_bucket[e][j]) > ki) ? 1 : 0;
            if (rank >= CAP) {
                unsigned n = ~(unsigned)(ki & 0xffffffffull);
                out[2 * NASSIGN + 1 + n] = 0.0f;
            }
        }
    }
    __syncthreads();

    if (tid < NEXP) { g_cnt[tid] = 0; g_probsum[tid] = 0.0f; }
    if (tid == 0)   { g_done = 0u; g_ticket = 0u; __threadfence(); }
}

extern "C" void kernel_launch(void* const* d_in, const int* in_sizes, int n_in,
                              void* d_out, int out_size) {
    const float* x  = (const float*)d_in[0];
    const float* wg = (const float*)d_in[1];
    float* out = (float*)d_out;
    (void)in_sizes; (void)n_in; (void)out_size;

    cudaFuncSetAttribute(router_main, cudaFuncAttributeMaxDynamicSharedMemorySize,
                         SMEM_DYN);

    router_main<<<NBLK, THREADS, SMEM_DYN>>>(x, wg, out);
}